// round 17
// baseline (speedup 1.0000x reference)
#include <cuda_runtime.h>
#include <cuda_fp16.h>
#include <cstdint>

// ============================================================================
// CourierEncoder fused MLP, sm_103 plain-target mma.sync FP16 path, round 17.
//   emb[B,384] -> h1 = lrelu(emb@w1+b1) -> out = lrelu(h1@w2+b2)
// fp16 operands (11-bit significand == tf32), fp32 accumulate, m16n8k16.
// == 4-WAY PHASE MIXING ==
// CTA = 32 rows, 128 threads = 4 warps, warp tile 32x64 (mf=2, nf=8,
// 64 accs/lane); __launch_bounds__(128,4) -> 4 CTAs/SM, 16 warps/SM.
// Same per-row L1 traffic as the 64x32 shape (zero-sum), but 4 independent
// CTAs interleave emb/epilogue phases against each other's gemm phases.
// B loads: split half-buffers bbA/bbB (32 regs), each half reloaded right
// after its last use in the previous k-pair. Grid = 8192 (no tail).
// Low-LDS fragment-native emb; w2 output-column permuted -> STG.128.
// ============================================================================

static constexpr float NEG_SLOPEF = 0.01f;
static constexpr int KS1 = 24;   // 384/16 k-steps, layer 1
static constexpr int KS2 = 16;   // 256/16 k-steps, layer 2
static constexpr int SP1 = KS1 / 2;
static constexpr int SP2 = KS2 / 2;
static constexpr int CROWS = 32;
static constexpr int GRID  = 262144 / CROWS;   // 8192, exact

// fragment-blocked fp16 weights: [n8][sp][lane] uint4
__device__ uint4 g_w1B[32 * SP1 * 32];
__device__ uint4 g_w2B[32 * SP2 * 32];

// ---- smem layout (f32 words) ----
static constexpr int SM_A1   = 0;              // 2 mt * 24 s * 32 * 4 = 6144 words
static constexpr int SM_A2   = 6144;           // 2 * 16 * 32 * 4 = 4096 words
static constexpr int SM_FR   = 10240;          // 512
static constexpr int SM_WT   = SM_FR + 512;    // 128
static constexpr int SM_BT   = SM_WT + 128;    // 128
static constexpr int SM_B1   = SM_BT + 128;    // 256
static constexpr int SM_B2   = SM_B1 + 256;    // 256
static constexpr int SM_X    = SM_B2 + 256;    // 32
static constexpr int SM_Y    = SM_X + 32;      // 32
static constexpr int SM_T    = SM_Y + 32;      // 32
static constexpr int SMEM_WORDS = SM_T + 32;
static constexpr int SMEM_BYTES = SMEM_WORDS * 4;   // 46464 B -> 4 CTAs/SM

__device__ __forceinline__ float lrelu(float v) { return v >= 0.f ? v : NEG_SLOPEF * v; }

__device__ __forceinline__ void mma16(float* c, const uint32_t* a, uint32_t b0, uint32_t b1) {
    asm volatile(
        "mma.sync.aligned.m16n8k16.row.col.f32.f16.f16.f32 "
        "{%0,%1,%2,%3}, {%4,%5,%6,%7}, {%8,%9}, {%0,%1,%2,%3};"
        : "+f"(c[0]), "+f"(c[1]), "+f"(c[2]), "+f"(c[3])
        : "r"(a[0]), "r"(a[1]), "r"(a[2]), "r"(a[3]), "r"(b0), "r"(b1));
}

__device__ __forceinline__ uint32_t pack2(float lo, float hi) {
    __half2 h = __floats2half2_rn(lo, hi);
    return *(uint32_t*)&h;
}

// ---------------------------------------------------------------- prep kernel
// w1: fragment-blocked (tile n8 covers cols [8*n8, 8*n8+8)).
// w2: OUTPUT-PERMUTED for 8-tiles-per-warp: n8 = w*8 + nf, nf = 2e+d; n-slot g
//     holds actual column w*64 + e*16 + 4*(g>>1) + 2d + (g&1).
__global__ void courier_prep(const float* __restrict__ w1, const float* __restrict__ w2) {
    int i = blockIdx.x * blockDim.x + threadIdx.x;
    if (i < 32 * SP1 * 32) {
        int n8 = i / (SP1 * 32);
        int rem = i % (SP1 * 32);
        int sp = rem >> 5, lane = rem & 31;
        int g = lane >> 2, tg = lane & 3;
        int n = n8 * 8 + g;
        int k0 = 32 * sp + 2 * tg;
        int k1 = k0 + 16;
        uint4 v;
        v.x = pack2(w1[(k0)      * 256 + n], w1[(k0 + 1)  * 256 + n]);
        v.y = pack2(w1[(k0 + 8)  * 256 + n], w1[(k0 + 9)  * 256 + n]);
        v.z = pack2(w1[(k1)      * 256 + n], w1[(k1 + 1)  * 256 + n]);
        v.w = pack2(w1[(k1 + 8)  * 256 + n], w1[(k1 + 9)  * 256 + n]);
        g_w1B[i] = v;
    }
    int j = i - 32 * SP1 * 32;
    if (j >= 0 && j < 32 * SP2 * 32) {
        int n8 = j / (SP2 * 32);
        int rem = j % (SP2 * 32);
        int sp = rem >> 5, lane = rem & 31;
        int g = lane >> 2, tg = lane & 3;
        int nf = n8 & 7;
        int e = nf >> 1, d = nf & 1;
        int n = (n8 >> 3) * 64 + e * 16 + 4 * (g >> 1) + 2 * d + (g & 1);
        int k0 = 32 * sp + 2 * tg;
        int k1 = k0 + 16;
        uint4 v;
        v.x = pack2(w2[(k0)      * 256 + n], w2[(k0 + 1)  * 256 + n]);
        v.y = pack2(w2[(k0 + 8)  * 256 + n], w2[(k0 + 9)  * 256 + n]);
        v.z = pack2(w2[(k1)      * 256 + n], w2[(k1 + 1)  * 256 + n]);
        v.w = pack2(w2[(k1 + 8)  * 256 + n], w2[(k1 + 9)  * 256 + n]);
        g_w2B[j] = v;
    }
}

// ---------------------------------------------------------------- gemm core
// D[32,256] += A_packed * W_blocked. Warp tile 32x64 at warp w (0..3).
// Half-buffered B: bbA = tiles 0-3, bbB = tiles 4-7; each half reloaded for
// sp+1 immediately after its last use in sp.
template <int KS>
__device__ __forceinline__ void gemm_layer(const uint4* __restrict__ Wb,
                                           const uint4* __restrict__ smA4,
                                           int w, int lane,
                                           float acc[2][8][4]) {
    constexpr int SP = KS / 2;
    const uint4* bbase = Wb + (size_t)(w * 8) * SP * 32 + lane;

    uint4 bbA[4], bbB[4];
#pragma unroll
    for (int nf = 0; nf < 4; nf++) bbA[nf] = bbase[(nf * SP) * 32];
#pragma unroll
    for (int nf = 0; nf < 4; nf++) bbB[nf] = bbase[((nf + 4) * SP) * 32];

#pragma unroll
    for (int sp = 0; sp < SP; sp++) {
        // ---- h = 0 ----
        {
            const int s = 2 * sp;
            uint32_t a[2][4];
#pragma unroll
            for (int mf = 0; mf < 2; mf++) {
                uint4 av = smA4[(mf * KS + s) * 32 + lane];
                a[mf][0] = av.x; a[mf][1] = av.y; a[mf][2] = av.z; a[mf][3] = av.w;
            }
#pragma unroll
            for (int mf = 0; mf < 2; mf++)
#pragma unroll
                for (int nf = 0; nf < 4; nf++)
                    mma16(acc[mf][nf], a[mf], bbA[nf].x, bbA[nf].y);
#pragma unroll
            for (int mf = 0; mf < 2; mf++)
#pragma unroll
                for (int nf = 0; nf < 4; nf++)
                    mma16(acc[mf][nf + 4], a[mf], bbB[nf].x, bbB[nf].y);
        }
        // ---- h = 1 ----
        {
            const int s = 2 * sp + 1;
            uint32_t a[2][4];
#pragma unroll
            for (int mf = 0; mf < 2; mf++) {
                uint4 av = smA4[(mf * KS + s) * 32 + lane];
                a[mf][0] = av.x; a[mf][1] = av.y; a[mf][2] = av.z; a[mf][3] = av.w;
            }
            // use .z/.w of bbA, then reload bbA for sp+1
#pragma unroll
            for (int mf = 0; mf < 2; mf++)
#pragma unroll
                for (int nf = 0; nf < 4; nf++)
                    mma16(acc[mf][nf], a[mf], bbA[nf].z, bbA[nf].w);
            if (sp + 1 < SP) {
#pragma unroll
                for (int nf = 0; nf < 4; nf++)
                    bbA[nf] = bbase[(nf * SP + sp + 1) * 32];
            }
#pragma unroll
            for (int mf = 0; mf < 2; mf++)
#pragma unroll
                for (int nf = 0; nf < 4; nf++)
                    mma16(acc[mf][nf + 4], a[mf], bbB[nf].z, bbB[nf].w);
            if (sp + 1 < SP) {
#pragma unroll
                for (int nf = 0; nf < 4; nf++)
                    bbB[nf] = bbase[((nf + 4) * SP + sp + 1) * 32];
            }
        }
    }
}

// ---------------------------------------------------------------- main kernel
__global__ __launch_bounds__(128, 4)
void courier_main(const float* __restrict__ xy, const float* __restrict__ tin,
                  const float* __restrict__ w_sx, const float* __restrict__ b_sx,
                  const float* __restrict__ w_cx, const float* __restrict__ b_cx,
                  const float* __restrict__ w_sy, const float* __restrict__ b_sy,
                  const float* __restrict__ w_cy, const float* __restrict__ b_cy,
                  const float* __restrict__ w_t,  const float* __restrict__ b_t,
                  const float* __restrict__ b1,   const float* __restrict__ b2,
                  float* __restrict__ out) {
    extern __shared__ float sm[];
    uint4*  smA1 = (uint4*)(sm + SM_A1);
    uint4*  smA2 = (uint4*)(sm + SM_A2);
    float* sm_fr = sm + SM_FR;
    float* sm_wt = sm + SM_WT;
    float* sm_bt = sm + SM_BT;
    float* sm_b1 = sm + SM_B1;
    float* sm_b2 = sm + SM_B2;
    float* sm_x  = sm + SM_X;
    float* sm_y  = sm + SM_Y;
    float* sm_t  = sm + SM_T;

    const int tid  = threadIdx.x;
    const int lane = tid & 31;
    const int w    = tid >> 5;            // 0..3

    // ---- stage small params + per-row inputs ----
    if (tid < CROWS) {
        int row = blockIdx.x * CROWS + tid;
        float2 p = *(const float2*)(xy + 2 * row);
        sm_x[tid] = p.x;
        sm_y[tid] = p.y;
        sm_t[tid] = tin[row];
    }
    sm_wt[tid] = w_t[tid];
    sm_bt[tid] = b_t[tid];
    if (tid < 64) {
        sm_fr[tid]       = w_sx[tid];  sm_fr[64 + tid]  = b_sx[tid];
        sm_fr[128 + tid] = w_cx[tid];  sm_fr[192 + tid] = b_cx[tid];
        sm_fr[256 + tid] = w_sy[tid];  sm_fr[320 + tid] = b_sy[tid];
        sm_fr[384 + tid] = w_cy[tid];  sm_fr[448 + tid] = b_cy[tid];
    }
    sm_b1[tid] = b1[tid];  sm_b1[128 + tid] = b1[128 + tid];
    sm_b2[tid] = b2[tid];  sm_b2[128 + tid] = b2[128 + tid];
    __syncthreads();

    const int g = lane >> 2, tg = lane & 3;

    // ---- generate embedding A1 [32 x 384] FRAGMENT-NATIVE, LOW-LDS ----
    // warp w owns k-steps s in [6w, 6w+6), both mtiles; per-step freq consts
    // hoisted into registers and reused over rows.
    {
#pragma unroll
        for (int js = 0; js < 6; js++) {
            const int s  = 6 * w + js;
            const int k0 = 16 * s + 2 * tg;
            const bool isT    = (s >= 16);
            const bool useCos = ((s >> 2) & 1);
            float wA, wB, wC, wD, bA, bB, bC, bD;
            const float* inp;
            if (isT) {
                int i = k0 - 256;
                wA = sm_wt[i];     wB = sm_wt[i + 1];
                wC = sm_wt[i + 8]; wD = sm_wt[i + 9];
                bA = sm_bt[i];     bB = sm_bt[i + 1];
                bC = sm_bt[i + 8]; bD = sm_bt[i + 9];
                inp = sm_t;
            } else {
                int base = k0 + 64 * (s >> 2);
                wA = sm_fr[base];      wB = sm_fr[base + 1];
                wC = sm_fr[base + 8];  wD = sm_fr[base + 9];
                bA = sm_fr[base + 64]; bB = sm_fr[base + 65];
                bC = sm_fr[base + 72]; bD = sm_fr[base + 73];
                inp = (s >= 8) ? sm_y : sm_x;
            }
#pragma unroll
            for (int mt = 0; mt < 2; mt++) {
                int r0 = mt * 16 + g;
                float in0 = inp[r0], in1 = inp[r0 + 8];
                float aA0 = fmaf(in0, wA, bA), aB0 = fmaf(in0, wB, bB);
                float aC0 = fmaf(in0, wC, bC), aD0 = fmaf(in0, wD, bD);
                float aA1 = fmaf(in1, wA, bA), aB1 = fmaf(in1, wB, bB);
                float aC1 = fmaf(in1, wC, bC), aD1 = fmaf(in1, wD, bD);
                float vA0, vB0, vC0, vD0, vA1, vB1, vC1, vD1;
                if (isT) {
                    vA0 = lrelu(aA0); vB0 = lrelu(aB0);
                    vC0 = lrelu(aC0); vD0 = lrelu(aD0);
                    vA1 = lrelu(aA1); vB1 = lrelu(aB1);
                    vC1 = lrelu(aC1); vD1 = lrelu(aD1);
                } else if (useCos) {
                    vA0 = __cosf(aA0); vB0 = __cosf(aB0);
                    vC0 = __cosf(aC0); vD0 = __cosf(aD0);
                    vA1 = __cosf(aA1); vB1 = __cosf(aB1);
                    vC1 = __cosf(aC1); vD1 = __cosf(aD1);
                } else {
                    vA0 = __sinf(aA0); vB0 = __sinf(aB0);
                    vC0 = __sinf(aC0); vD0 = __sinf(aD0);
                    vA1 = __sinf(aA1); vB1 = __sinf(aB1);
                    vC1 = __sinf(aC1); vD1 = __sinf(aD1);
                }
                uint4 st;
                st.x = pack2(vA0, vB0);
                st.y = pack2(vA1, vB1);
                st.z = pack2(vC0, vD0);
                st.w = pack2(vC1, vD1);
                smA1[(mt * KS1 + s) * 32 + lane] = st;
            }
        }
    }
    __syncthreads();

    // ---- layer 1 ----
    float acc[2][8][4];
#pragma unroll
    for (int mf = 0; mf < 2; mf++)
#pragma unroll
        for (int nf = 0; nf < 8; nf++)
#pragma unroll
            for (int j = 0; j < 4; j++) acc[mf][nf][j] = 0.f;

    gemm_layer<KS1>(g_w1B, smA1, w, lane, acc);

    // ---- epilogue 1: bias + lrelu + fp16 -> A2 (separate buffer) ----
    // warp covers cols [w*64, w*64+64) -> layer-2 k-steps s2 = w*4 + e.
    {
#pragma unroll
        for (int mf = 0; mf < 2; mf++) {
#pragma unroll
            for (int e = 0; e < 4; e++) {
                int col0 = w * 64 + e * 16 + 2 * tg;
                int col1 = col0 + 8;
                uint4 st;
                st.x = pack2(lrelu(acc[mf][2*e][0]   + sm_b1[col0]),
                             lrelu(acc[mf][2*e][1]   + sm_b1[col0 + 1]));
                st.y = pack2(lrelu(acc[mf][2*e][2]   + sm_b1[col0]),
                             lrelu(acc[mf][2*e][3]   + sm_b1[col0 + 1]));
                st.z = pack2(lrelu(acc[mf][2*e+1][0] + sm_b1[col1]),
                             lrelu(acc[mf][2*e+1][1] + sm_b1[col1 + 1]));
                st.w = pack2(lrelu(acc[mf][2*e+1][2] + sm_b1[col1]),
                             lrelu(acc[mf][2*e+1][3] + sm_b1[col1 + 1]));
                int s2 = w * 4 + e;
                smA2[(mf * KS2 + s2) * 32 + lane] = st;
            }
        }
    }
    __syncthreads();

    // ---- layer 2 (w2 columns permuted in prep) ----
#pragma unroll
    for (int mf = 0; mf < 2; mf++)
#pragma unroll
        for (int nf = 0; nf < 8; nf++)
#pragma unroll
            for (int j = 0; j < 4; j++) acc[mf][nf][j] = 0.f;

    gemm_layer<KS2>(g_w2B, smA2, w, lane, acc);

    // ---- final epilogue: bias + lrelu, aligned STG.128 (no tail) ----
    {
        float* obase = out + (size_t)blockIdx.x * CROWS * 256;
#pragma unroll
        for (int mf = 0; mf < 2; mf++) {
            int r0 = mf * 16 + g;
#pragma unroll
            for (int e = 0; e < 4; e++) {
                int c = w * 64 + e * 16 + 4 * tg;
                float4 bv = *(const float4*)(sm_b2 + c);
                float4 v0, v1;
                v0.x = lrelu(acc[mf][2*e][0]   + bv.x);
                v0.y = lrelu(acc[mf][2*e][1]   + bv.y);
                v0.z = lrelu(acc[mf][2*e+1][0] + bv.z);
                v0.w = lrelu(acc[mf][2*e+1][1] + bv.w);
                v1.x = lrelu(acc[mf][2*e][2]   + bv.x);
                v1.y = lrelu(acc[mf][2*e][3]   + bv.y);
                v1.z = lrelu(acc[mf][2*e+1][2] + bv.z);
                v1.w = lrelu(acc[mf][2*e+1][3] + bv.w);
                *(float4*)(obase + r0 * 256 + c)       = v0;
                *(float4*)(obase + (r0 + 8) * 256 + c) = v1;
            }
        }
    }
}

// ---------------------------------------------------------------- launcher
extern "C" void kernel_launch(void* const* d_in, const int* in_sizes, int n_in,
                              void* d_out, int out_size) {
    const float* xy   = (const float*)d_in[0];
    const float* t    = (const float*)d_in[1];
    const float* w_sx = (const float*)d_in[2];
    const float* b_sx = (const float*)d_in[3];
    const float* w_cx = (const float*)d_in[4];
    const float* b_cx = (const float*)d_in[5];
    const float* w_sy = (const float*)d_in[6];
    const float* b_sy = (const float*)d_in[7];
    const float* w_cy = (const float*)d_in[8];
    const float* b_cy = (const float*)d_in[9];
    const float* w_t  = (const float*)d_in[10];
    const float* b_t  = (const float*)d_in[11];
    const float* w1   = (const float*)d_in[12];
    const float* b1   = (const float*)d_in[13];
    const float* w2   = (const float*)d_in[14];
    const float* b2   = (const float*)d_in[15];
    float* out = (float*)d_out;

    courier_prep<<<128, 256>>>(w1, w2);

    static bool attr_set = false;
    if (!attr_set) {
        cudaFuncSetAttribute(courier_main, cudaFuncAttributeMaxDynamicSharedMemorySize,
                             SMEM_BYTES);
        attr_set = true;
    }

    courier_main<<<GRID, 128, SMEM_BYTES>>>(xy, t, w_sx, b_sx, w_cx, b_cx,
                                            w_sy, b_sy, w_cy, b_cy,
                                            w_t, b_t, b1, b2, out);
}